// round 14
// baseline (speedup 1.0000x reference)
#include <cuda_runtime.h>
#include <cuda_bf16.h>

// Fractal2DDiff — SIMT f32x2 v9: warp-pair split + factored inner product.
//  * p·l·D + p·R = p·(l·D + R): per (node,col,q) two FMA2s and NO MUL2 —
//    11% less fma-pipe demand than v8, identical memory traffic.
//  * Each 32-point tile co-owned by two warps (column halves); 20 warps/SM.
//  * persistent 148 CTAs; rank-1 first step; folded final step; one
//    normalization at the end (L,R row-stochastic, CP rows sum to 1).

#define N_NODES   64
#define N_CLASSES 16
#define NTILES    10
#define WARPS     (2 * NTILES)
#define TPB       (WARPS * 32)       // 640
#define PPB       (NTILES * 32)      // 320 points per batch
#define PSTRIDE   36

typedef unsigned long long u64;

__device__ float g_D[N_NODES * N_NODES];
__device__ float g_R[N_NODES * N_NODES];
__device__ float g_DC[N_NODES * N_CLASSES];
__device__ float g_RC[N_NODES * N_CLASSES];
__device__ float g_par[256];

// ---------------------------------------------------------------------------
__global__ void fractal_setup_kernel(const float* __restrict__ sp,
                                     const float* __restrict__ dir_logits,
                                     const float* __restrict__ class_logits,
                                     const float* __restrict__ child_logits) {
    __shared__ float sCP[N_NODES * N_CLASSES];
    int t = threadIdx.x;

    {
        const float* cr = class_logits + t * N_CLASSES;
        float m = -1e30f;
        for (int i = 0; i < N_CLASSES; i++) m = fmaxf(m, cr[i]);
        float s = 0.0f;
        for (int i = 0; i < N_CLASSES; i++) s += expf(cr[i] - m);
        float inv = 1.0f / s;
        for (int i = 0; i < N_CLASSES; i++) sCP[t * N_CLASSES + i] = expf(cr[i] - m) * inv;
    }
    __syncthreads();

    const float* lr = child_logits + (size_t)t * 2 * N_NODES;
    const float* rr = lr + N_NODES;
    float Lv[64], Rv[64], Dv[64];
    {
        float m = -1e30f;
        for (int i = 0; i < 64; i++) m = fmaxf(m, lr[i]);
        float s = 0.0f;
        for (int i = 0; i < 64; i++) s += expf(lr[i] - m);
        float inv = 1.0f / s;
        for (int i = 0; i < 64; i++) Lv[i] = expf(lr[i] - m) * inv;
    }
    {
        float m = -1e30f;
        for (int i = 0; i < 64; i++) m = fmaxf(m, rr[i]);
        float s = 0.0f;
        for (int i = 0; i < 64; i++) s += expf(rr[i] - m);
        float inv = 1.0f / s;
        for (int i = 0; i < 64; i++) Rv[i] = expf(rr[i] - m) * inv;
    }
    for (int i = 0; i < 64; i++) {
        Dv[i] = Lv[i] - Rv[i];
        g_D[t * 64 + i] = Dv[i];
        g_R[t * 64 + i] = Rv[i];
    }
    for (int jc = 0; jc < N_CLASSES; jc++) {
        float ds = 0.0f, rs = 0.0f;
        for (int j = 0; j < 64; j++) {
            ds += Dv[j] * sCP[j * N_CLASSES + jc];
            rs += Rv[j] * sCP[j * N_CLASSES + jc];
        }
        g_DC[t * N_CLASSES + jc] = ds;
        g_RC[t * N_CLASSES + jc] = rs;
    }
    g_par[t]      = expf(-sp[t]);
    g_par[64 + t] = 1.0f / (1.0f + expf(-dir_logits[t]));
    if (t == 0)
        for (int j = 0; j < 64; j++) { g_par[128 + j] = Dv[j]; g_par[192 + j] = Rv[j]; }
}

#define FMA2(acc, a, b) \
    asm("fma.rn.f32x2 %0, %1, %2, %0;" : "+l"(acc) : "l"(a), "l"(b))
#define FMA2D(dst, a, b, c) \
    asm("fma.rn.f32x2 %0, %1, %2, %3;" : "=l"(dst) : "l"(a), "l"(b), "l"(c))
#define PACK_DUP(d, s) \
    asm("mov.b64 %0, {%1, %1};" : "=l"(d) : "f"(s))
#define UNPACK2(lo, hi, v) \
    asm("mov.b64 {%0, %1}, %2;" : "=f"(lo), "=f"(hi) : "l"(v))
#define PAIR_BAR(tile) \
    asm volatile("bar.sync %0, 64;" :: "r"((tile) + 1) : "memory")

__device__ __forceinline__ int decode_depth(const void* mdp) {
    int v = *reinterpret_cast<const int*>(mdp);
    if (v >= 1 && v <= 1000) return v;
    float f = __int_as_float(v);
    if (f >= 1.0f && f <= 1000.0f) return (int)f;
    return 10;
}

// smem floats: Ds 4096 | Rs 4096 | DCs 1024 | RCs 1024 | PAR 256 |
//              state NTILES * 2 * 64 * PSTRIDE
#define SMEM_FLOATS (4096 + 4096 + 1024 + 1024 + 256 + NTILES * 2 * 64 * PSTRIDE)
#define SMEM_BYTES  (SMEM_FLOATS * 4)

__global__ __launch_bounds__(TPB, 1)
void fractal_main_kernel(const float* __restrict__ x_pos,
                         const float* __restrict__ y_pos,
                         const void*  __restrict__ max_depth_ptr,
                         float* __restrict__ out,
                         int B, int nbatch) {
    extern __shared__ float sm[];
    float* Ds  = sm;
    float* Rs  = Ds + 4096;
    float* DCs = Rs + 4096;
    float* RCs = DCs + 1024;
    float* PAR = RCs + 1024;
    float* ST  = PAR + 256;

    const int tid  = threadIdx.x;
    const int wid  = tid >> 5;
    const int lane = tid & 31;
    const int tile = wid >> 1;
    const int sub  = wid & 1;
    const int cb   = sub * 32;
    const int cg   = lane & 7;
    const int pg   = lane >> 3;

    for (int i = tid; i < 4096; i += TPB) { Ds[i] = g_D[i]; Rs[i] = g_R[i]; }
    for (int i = tid; i < 1024; i += TPB) { DCs[i] = g_DC[i]; RCs[i] = g_RC[i]; }
    if (tid < 256) PAR[tid] = g_par[tid];
    __syncthreads();

    float* Pw  = ST + tile * (2 * 64 * PSTRIDE);
    float* Lfw = Pw + 64 * PSTRIDE;

    int md = decode_depth(max_depth_ptr);
    if (md < 2) md = 2;
    const int full_iters = md - 2;

    const float* pbase = Pw + 8 * pg;
    const float* lbase = Lfw + 8 * pg;

    for (int bi = blockIdx.x; bi < nbatch; bi += gridDim.x) {
        const long long my_pt = (long long)bi * PPB + tile * 32 + lane;
        const bool inr = (my_pt < B);

        const float x = inr ? x_pos[my_pt] : 0.5f;
        const float y = inr ? y_pos[my_pt] : 0.5f;
        const float ex = __expf(x), ey = __expf(y);

        float l0;
        {
            float t0 = PAR[0], d0 = PAR[64];
            float hl = __fdividef(1.0f, 1.0f + ex * t0);
            float vl = __fdividef(1.0f, 1.0f + ey * t0);
            l0 = hl + d0 * (vl - hl);
        }
        // init split by node half: sub 0 -> nodes 0..31, sub 1 -> nodes 32..63
        #pragma unroll 8
        for (int k = 0; k < 32; ++k) {
            int n = cb + k;
            float tn = PAR[n], d = PAR[64 + n];
            float hl = __fdividef(1.0f, 1.0f + ex * tn);
            float vl = __fdividef(1.0f, 1.0f + ey * tn);
            Lfw[n * PSTRIDE + lane] = hl + d * (vl - hl);
            Pw[n * PSTRIDE + lane]  = fmaf(l0, PAR[128 + n], PAR[192 + n]);
        }
        PAIR_BAR(tile);

        // ------- full iterations: acc[c][q], c = 4 cols (cb+4cg+c), q = 4 pt-pairs
        for (int it = 0; it < full_iters; ++it) {
            u64 acc[4][4];
            #pragma unroll
            for (int c = 0; c < 4; c++)
                #pragma unroll
                for (int q = 0; q < 4; q++) acc[c][q] = 0ull;

            #pragma unroll 8
            for (int n = 0; n < N_NODES; ++n) {
                ulonglong2 dt = *reinterpret_cast<const ulonglong2*>(Ds + n * 64 + cb + 4 * cg);
                ulonglong2 rt = *reinterpret_cast<const ulonglong2*>(Rs + n * 64 + cb + 4 * cg);

                const float* prow = pbase + n * PSTRIDE;
                const float* lrow = lbase + n * PSTRIDE;
                ulonglong2 pA = *reinterpret_cast<const ulonglong2*>(prow);
                ulonglong2 pB = *reinterpret_cast<const ulonglong2*>(prow + 4);
                ulonglong2 lA = *reinterpret_cast<const ulonglong2*>(lrow);
                ulonglong2 lB = *reinterpret_cast<const ulonglong2*>(lrow + 4);

                u64 p2[4] = { pA.x, pA.y, pB.x, pB.y };
                u64 l2[4] = { lA.x, lA.y, lB.x, lB.y };

                float dsc[4], rsc[4];
                UNPACK2(dsc[0], dsc[1], dt.x); UNPACK2(dsc[2], dsc[3], dt.y);
                UNPACK2(rsc[0], rsc[1], rt.x); UNPACK2(rsc[2], rsc[3], rt.y);

                // factored: acc[c][q] += p * (l*D + R)
                #pragma unroll
                for (int c = 0; c < 4; c++) {
                    u64 dd, rr;
                    PACK_DUP(dd, dsc[c]);
                    PACK_DUP(rr, rsc[c]);
                    #pragma unroll
                    for (int q = 0; q < 4; q++) {
                        u64 t;
                        FMA2D(t, l2[q], dd, rr);
                        FMA2(acc[c][q], p2[q], t);
                    }
                }
            }

            PAIR_BAR(tile);
            #pragma unroll
            for (int c = 0; c < 4; c++) {
                int col = cb + 4 * cg + c;
                ulonglong2* dst = reinterpret_cast<ulonglong2*>(Pw + col * PSTRIDE + 8 * pg);
                ulonglong2 v0; v0.x = acc[c][0]; v0.y = acc[c][1];
                ulonglong2 v1; v1.x = acc[c][2]; v1.y = acc[c][3];
                dst[0] = v0;
                dst[1] = v1;
            }
            PAIR_BAR(tile);
        }

        // ------- folded final step: 1 class per lane (cls = 8*sub + cg) -------
        {
            const int cls = 8 * sub + cg;
            u64 fac[4];
            #pragma unroll
            for (int q = 0; q < 4; q++) fac[q] = 0ull;

            #pragma unroll 8
            for (int n = 0; n < N_NODES; ++n) {
                float dcv = DCs[n * N_CLASSES + cls];
                float rcv = RCs[n * N_CLASSES + cls];

                const float* prow = pbase + n * PSTRIDE;
                const float* lrow = lbase + n * PSTRIDE;
                ulonglong2 pA = *reinterpret_cast<const ulonglong2*>(prow);
                ulonglong2 pB = *reinterpret_cast<const ulonglong2*>(prow + 4);
                ulonglong2 lA = *reinterpret_cast<const ulonglong2*>(lrow);
                ulonglong2 lB = *reinterpret_cast<const ulonglong2*>(lrow + 4);

                u64 p2[4] = { pA.x, pA.y, pB.x, pB.y };
                u64 l2[4] = { lA.x, lA.y, lB.x, lB.y };

                u64 dd, rr;
                PACK_DUP(dd, dcv);
                PACK_DUP(rr, rcv);
                #pragma unroll
                for (int q = 0; q < 4; q++) {
                    u64 t;
                    FMA2D(t, l2[q], dd, rr);
                    FMA2(fac[q], p2[q], t);
                }
            }

            PAIR_BAR(tile);
            {
                ulonglong2* dst = reinterpret_cast<ulonglong2*>(Pw + cls * PSTRIDE + 8 * pg);
                ulonglong2 v0; v0.x = fac[0]; v0.y = fac[1];
                ulonglong2 v1; v1.x = fac[2]; v1.y = fac[3];
                dst[0] = v0;
                dst[1] = v1;
            }
            PAIR_BAR(tile);
        }

        // ------- gather own point, normalize, store (warp sub==0 only) -------
        if (sub == 0 && inr) {
            float o[16], s = 0.0f;
            #pragma unroll
            for (int c = 0; c < 16; c++) { o[c] = Pw[c * PSTRIDE + lane]; s += o[c]; }
            float inv = 1.0f / fmaxf(s, 1e-10f);
            float4* o4 = reinterpret_cast<float4*>(out + my_pt * N_CLASSES);
            #pragma unroll
            for (int k = 0; k < 4; k++) {
                float4 v;
                v.x = o[4 * k] * inv;     v.y = o[4 * k + 1] * inv;
                v.z = o[4 * k + 2] * inv; v.w = o[4 * k + 3] * inv;
                o4[k] = v;
            }
        }
    }
}

// ---------------------------------------------------------------------------
extern "C" void kernel_launch(void* const* d_in, const int* in_sizes, int n_in,
                              void* d_out, int out_size) {
    const float* x_pos = (const float*)d_in[0];
    const float* y_pos = (const float*)d_in[1];
    const float* sp    = (const float*)d_in[2];
    const float* dirl  = (const float*)d_in[3];
    const float* cls   = (const float*)d_in[4];
    const float* child = (const float*)d_in[5];
    const void*  mdp   = d_in[6];
    float* out = (float*)d_out;

    int B = in_sizes[0];
    int nbatch = (B + PPB - 1) / PPB;
    int grid = nbatch < 148 ? nbatch : 148;

    cudaFuncSetAttribute(fractal_main_kernel,
                         cudaFuncAttributeMaxDynamicSharedMemorySize, SMEM_BYTES);

    fractal_setup_kernel<<<1, 64>>>(sp, dirl, cls, child);

    fractal_main_kernel<<<grid, TPB, SMEM_BYTES>>>(x_pos, y_pos, mdp, out, B, nbatch);
}

// round 15
// speedup vs baseline: 1.0039x; 1.0039x over previous
#include <cuda_runtime.h>
#include <cuda_bf16.h>

// Fractal2DDiff — SIMT f32x2 v10: warp-pair split + (p, a)-state.
//  * State arrays are p and a = p∘left (instead of p and left): the loop is
//    pure acc += a·D + p·R — 32 FMA2/node, ZERO MUL2 (-11% fma demand vs v8,
//    identical memory pattern/ILP). left for writeback (a_next = p_next∘l,
//    own 4 cols x 8 pts) lives in 16 u64 registers, captured once per batch
//    via a staging pass through the P array.
//  * Each 32-pt tile co-owned by two warps (column halves); 20 warps/SM.
//  * persistent 148 CTAs; rank-1 first step; folded final step
//    (a@DC + p@RC — native in the new state); one end normalization.

#define N_NODES   64
#define N_CLASSES 16
#define NTILES    10
#define WARPS     (2 * NTILES)
#define TPB       (WARPS * 32)       // 640
#define PPB       (NTILES * 32)      // 320 points per batch
#define PSTRIDE   36

typedef unsigned long long u64;

__device__ float g_D[N_NODES * N_NODES];
__device__ float g_R[N_NODES * N_NODES];
__device__ float g_DC[N_NODES * N_CLASSES];
__device__ float g_RC[N_NODES * N_CLASSES];
__device__ float g_par[256];

// ---------------------------------------------------------------------------
__global__ void fractal_setup_kernel(const float* __restrict__ sp,
                                     const float* __restrict__ dir_logits,
                                     const float* __restrict__ class_logits,
                                     const float* __restrict__ child_logits) {
    __shared__ float sCP[N_NODES * N_CLASSES];
    int t = threadIdx.x;

    {
        const float* cr = class_logits + t * N_CLASSES;
        float m = -1e30f;
        for (int i = 0; i < N_CLASSES; i++) m = fmaxf(m, cr[i]);
        float s = 0.0f;
        for (int i = 0; i < N_CLASSES; i++) s += expf(cr[i] - m);
        float inv = 1.0f / s;
        for (int i = 0; i < N_CLASSES; i++) sCP[t * N_CLASSES + i] = expf(cr[i] - m) * inv;
    }
    __syncthreads();

    const float* lr = child_logits + (size_t)t * 2 * N_NODES;
    const float* rr = lr + N_NODES;
    float Lv[64], Rv[64], Dv[64];
    {
        float m = -1e30f;
        for (int i = 0; i < 64; i++) m = fmaxf(m, lr[i]);
        float s = 0.0f;
        for (int i = 0; i < 64; i++) s += expf(lr[i] - m);
        float inv = 1.0f / s;
        for (int i = 0; i < 64; i++) Lv[i] = expf(lr[i] - m) * inv;
    }
    {
        float m = -1e30f;
        for (int i = 0; i < 64; i++) m = fmaxf(m, rr[i]);
        float s = 0.0f;
        for (int i = 0; i < 64; i++) s += expf(rr[i] - m);
        float inv = 1.0f / s;
        for (int i = 0; i < 64; i++) Rv[i] = expf(rr[i] - m) * inv;
    }
    for (int i = 0; i < 64; i++) {
        Dv[i] = Lv[i] - Rv[i];
        g_D[t * 64 + i] = Dv[i];
        g_R[t * 64 + i] = Rv[i];
    }
    for (int jc = 0; jc < N_CLASSES; jc++) {
        float ds = 0.0f, rs = 0.0f;
        for (int j = 0; j < 64; j++) {
            ds += Dv[j] * sCP[j * N_CLASSES + jc];
            rs += Rv[j] * sCP[j * N_CLASSES + jc];
        }
        g_DC[t * N_CLASSES + jc] = ds;
        g_RC[t * N_CLASSES + jc] = rs;
    }
    g_par[t]      = expf(-sp[t]);
    g_par[64 + t] = 1.0f / (1.0f + expf(-dir_logits[t]));
    if (t == 0)
        for (int j = 0; j < 64; j++) { g_par[128 + j] = Dv[j]; g_par[192 + j] = Rv[j]; }
}

#define FMA2(acc, a, b) \
    asm("fma.rn.f32x2 %0, %1, %2, %0;" : "+l"(acc) : "l"(a), "l"(b))
#define MUL2(d, a, b) \
    asm("mul.rn.f32x2 %0, %1, %2;" : "=l"(d) : "l"(a), "l"(b))
#define PACK_DUP(d, s) \
    asm("mov.b64 %0, {%1, %1};" : "=l"(d) : "f"(s))
#define UNPACK2(lo, hi, v) \
    asm("mov.b64 {%0, %1}, %2;" : "=f"(lo), "=f"(hi) : "l"(v))
#define PAIR_BAR(tile) \
    asm volatile("bar.sync %0, 64;" :: "r"((tile) + 1) : "memory")

__device__ __forceinline__ int decode_depth(const void* mdp) {
    int v = *reinterpret_cast<const int*>(mdp);
    if (v >= 1 && v <= 1000) return v;
    float f = __int_as_float(v);
    if (f >= 1.0f && f <= 1000.0f) return (int)f;
    return 10;
}

// smem floats: Ds 4096 | Rs 4096 | DCs 1024 | RCs 1024 | PAR 256 |
//              state NTILES * 2 * 64 * PSTRIDE   (P and A arrays)
#define SMEM_FLOATS (4096 + 4096 + 1024 + 1024 + 256 + NTILES * 2 * 64 * PSTRIDE)
#define SMEM_BYTES  (SMEM_FLOATS * 4)

__global__ __launch_bounds__(TPB, 1)
void fractal_main_kernel(const float* __restrict__ x_pos,
                         const float* __restrict__ y_pos,
                         const void*  __restrict__ max_depth_ptr,
                         float* __restrict__ out,
                         int B, int nbatch) {
    extern __shared__ float sm[];
    float* Ds  = sm;
    float* Rs  = Ds + 4096;
    float* DCs = Rs + 4096;
    float* RCs = DCs + 1024;
    float* PAR = RCs + 1024;
    float* ST  = PAR + 256;

    const int tid  = threadIdx.x;
    const int wid  = tid >> 5;
    const int lane = tid & 31;
    const int tile = wid >> 1;
    const int sub  = wid & 1;
    const int cb   = sub * 32;
    const int cg   = lane & 7;
    const int pg   = lane >> 3;

    for (int i = tid; i < 4096; i += TPB) { Ds[i] = g_D[i]; Rs[i] = g_R[i]; }
    for (int i = tid; i < 1024; i += TPB) { DCs[i] = g_DC[i]; RCs[i] = g_RC[i]; }
    if (tid < 256) PAR[tid] = g_par[tid];
    __syncthreads();

    float* Pw = ST + tile * (2 * 64 * PSTRIDE);
    float* Aw = Pw + 64 * PSTRIDE;

    int md = decode_depth(max_depth_ptr);
    if (md < 2) md = 2;
    const int full_iters = md - 2;

    const float* pbase = Pw + 8 * pg;
    const float* abase = Aw + 8 * pg;

    for (int bi = blockIdx.x; bi < nbatch; bi += gridDim.x) {
        const long long my_pt = (long long)bi * PPB + tile * 32 + lane;
        const bool inr = (my_pt < B);

        const float x = inr ? x_pos[my_pt] : 0.5f;
        const float y = inr ? y_pos[my_pt] : 0.5f;
        const float ex = __expf(x), ey = __expf(y);

        // --- stage left into Pw (own node half, own point column) ---
        #pragma unroll 8
        for (int k = 0; k < 32; ++k) {
            int n = cb + k;
            float tn = PAR[n], d = PAR[64 + n];
            float hl = __fdividef(1.0f, 1.0f + ex * tn);
            float vl = __fdividef(1.0f, 1.0f + ey * tn);
            Pw[n * PSTRIDE + lane] = hl + d * (vl - hl);
        }
        PAIR_BAR(tile);

        // --- capture l0 and the lane's writeback left-tile (4 cols x 4 pt-pairs)
        const float l0 = Pw[lane];
        u64 lq[4][4];
        #pragma unroll
        for (int c = 0; c < 4; c++) {
            int col = cb + 4 * cg + c;
            const u64* lrow = reinterpret_cast<const u64*>(Pw + col * PSTRIDE + 8 * pg);
            #pragma unroll
            for (int q = 0; q < 4; q++) lq[c][q] = lrow[q];
        }
        PAIR_BAR(tile);

        // --- init state after rank-1 first step: p1 = R0 + l0*D0 ; a1 = p1*l
        #pragma unroll 8
        for (int k = 0; k < 32; ++k) {
            int n = cb + k;
            float lv = Pw[n * PSTRIDE + lane];
            float p1 = fmaf(l0, PAR[128 + n], PAR[192 + n]);
            Pw[n * PSTRIDE + lane] = p1;
            Aw[n * PSTRIDE + lane] = p1 * lv;
        }
        PAIR_BAR(tile);

        // ------- full iterations: acc += a@D + p@R (no MUL2 in loop) -------
        for (int it = 0; it < full_iters; ++it) {
            u64 acc[4][4];
            #pragma unroll
            for (int c = 0; c < 4; c++)
                #pragma unroll
                for (int q = 0; q < 4; q++) acc[c][q] = 0ull;

            #pragma unroll 8
            for (int n = 0; n < N_NODES; ++n) {
                ulonglong2 dt = *reinterpret_cast<const ulonglong2*>(Ds + n * 64 + cb + 4 * cg);
                ulonglong2 rt = *reinterpret_cast<const ulonglong2*>(Rs + n * 64 + cb + 4 * cg);

                const float* prow = pbase + n * PSTRIDE;
                const float* arow = abase + n * PSTRIDE;
                ulonglong2 pA = *reinterpret_cast<const ulonglong2*>(prow);
                ulonglong2 pB = *reinterpret_cast<const ulonglong2*>(prow + 4);
                ulonglong2 aA = *reinterpret_cast<const ulonglong2*>(arow);
                ulonglong2 aB = *reinterpret_cast<const ulonglong2*>(arow + 4);

                u64 p2[4] = { pA.x, pA.y, pB.x, pB.y };
                u64 a2[4] = { aA.x, aA.y, aB.x, aB.y };

                float dsc[4], rsc[4];
                UNPACK2(dsc[0], dsc[1], dt.x); UNPACK2(dsc[2], dsc[3], dt.y);
                UNPACK2(rsc[0], rsc[1], rt.x); UNPACK2(rsc[2], rsc[3], rt.y);

                #pragma unroll
                for (int c = 0; c < 4; c++) {
                    u64 dd, rr;
                    PACK_DUP(dd, dsc[c]);
                    PACK_DUP(rr, rsc[c]);
                    #pragma unroll
                    for (int q = 0; q < 4; q++) {
                        FMA2(acc[c][q], a2[q], dd);
                        FMA2(acc[c][q], p2[q], rr);
                    }
                }
            }

            PAIR_BAR(tile);
            #pragma unroll
            for (int c = 0; c < 4; c++) {
                int col = cb + 4 * cg + c;
                u64 an[4];
                #pragma unroll
                for (int q = 0; q < 4; q++) MUL2(an[q], acc[c][q], lq[c][q]);
                ulonglong2* pdst = reinterpret_cast<ulonglong2*>(Pw + col * PSTRIDE + 8 * pg);
                ulonglong2* adst = reinterpret_cast<ulonglong2*>(Aw + col * PSTRIDE + 8 * pg);
                ulonglong2 v0; v0.x = acc[c][0]; v0.y = acc[c][1];
                ulonglong2 v1; v1.x = acc[c][2]; v1.y = acc[c][3];
                ulonglong2 w0; w0.x = an[0]; w0.y = an[1];
                ulonglong2 w1; w1.x = an[2]; w1.y = an[3];
                pdst[0] = v0; pdst[1] = v1;
                adst[0] = w0; adst[1] = w1;
            }
            PAIR_BAR(tile);
        }

        // ------- folded final step: out = a@DC + p@RC; 1 class per lane -------
        {
            const int cls = 8 * sub + cg;
            u64 fac[4];
            #pragma unroll
            for (int q = 0; q < 4; q++) fac[q] = 0ull;

            #pragma unroll 8
            for (int n = 0; n < N_NODES; ++n) {
                float dcv = DCs[n * N_CLASSES + cls];
                float rcv = RCs[n * N_CLASSES + cls];

                const float* prow = pbase + n * PSTRIDE;
                const float* arow = abase + n * PSTRIDE;
                ulonglong2 pA = *reinterpret_cast<const ulonglong2*>(prow);
                ulonglong2 pB = *reinterpret_cast<const ulonglong2*>(prow + 4);
                ulonglong2 aA = *reinterpret_cast<const ulonglong2*>(arow);
                ulonglong2 aB = *reinterpret_cast<const ulonglong2*>(arow + 4);

                u64 p2[4] = { pA.x, pA.y, pB.x, pB.y };
                u64 a2[4] = { aA.x, aA.y, aB.x, aB.y };

                u64 dd, rr;
                PACK_DUP(dd, dcv);
                PACK_DUP(rr, rcv);
                #pragma unroll
                for (int q = 0; q < 4; q++) {
                    FMA2(fac[q], a2[q], dd);
                    FMA2(fac[q], p2[q], rr);
                }
            }

            PAIR_BAR(tile);
            {
                ulonglong2* dst = reinterpret_cast<ulonglong2*>(Pw + cls * PSTRIDE + 8 * pg);
                ulonglong2 v0; v0.x = fac[0]; v0.y = fac[1];
                ulonglong2 v1; v1.x = fac[2]; v1.y = fac[3];
                dst[0] = v0;
                dst[1] = v1;
            }
            PAIR_BAR(tile);
        }

        // ------- gather own point, normalize, store (warp sub==0 only) -------
        if (sub == 0 && inr) {
            float o[16], s = 0.0f;
            #pragma unroll
            for (int c = 0; c < 16; c++) { o[c] = Pw[c * PSTRIDE + lane]; s += o[c]; }
            float inv = 1.0f / fmaxf(s, 1e-10f);
            float4* o4 = reinterpret_cast<float4*>(out + my_pt * N_CLASSES);
            #pragma unroll
            for (int k = 0; k < 4; k++) {
                float4 v;
                v.x = o[4 * k] * inv;     v.y = o[4 * k + 1] * inv;
                v.z = o[4 * k + 2] * inv; v.w = o[4 * k + 3] * inv;
                o4[k] = v;
            }
        }
        PAIR_BAR(tile);   // gather reads done before next batch's staging writes
    }
}

// ---------------------------------------------------------------------------
extern "C" void kernel_launch(void* const* d_in, const int* in_sizes, int n_in,
                              void* d_out, int out_size) {
    const float* x_pos = (const float*)d_in[0];
    const float* y_pos = (const float*)d_in[1];
    const float* sp    = (const float*)d_in[2];
    const float* dirl  = (const float*)d_in[3];
    const float* cls   = (const float*)d_in[4];
    const float* child = (const float*)d_in[5];
    const void*  mdp   = d_in[6];
    float* out = (float*)d_out;

    int B = in_sizes[0];
    int nbatch = (B + PPB - 1) / PPB;
    int grid = nbatch < 148 ? nbatch : 148;

    cudaFuncSetAttribute(fractal_main_kernel,
                         cudaFuncAttributeMaxDynamicSharedMemorySize, SMEM_BYTES);

    fractal_setup_kernel<<<1, 64>>>(sp, dirl, cls, child);

    fractal_main_kernel<<<grid, TPB, SMEM_BYTES>>>(x_pos, y_pos, mdp, out, B, nbatch);
}

// round 16
// speedup vs baseline: 1.0412x; 1.0372x over previous
#include <cuda_runtime.h>
#include <cuda_bf16.h>

// Fractal2DDiff — SIMT f32x2 v11: v8 (best: 2707us) + dynamic tile queue.
//  * Warp-pair column split (4 cols x 8 pts per lane), 20 warps/SM.
//  * Pairs pull 32-pt tiles from a global atomic counter: removes the
//    22-vs-23 static-assignment tail (~3.7%). Counter reset each launch by
//    the setup kernel (same stream => ordered; deterministic output).
//  * rank-1 first step; folded final step (D@CP, R@CP); one normalization.

#define N_NODES   64
#define N_CLASSES 16
#define NTILES    10
#define WARPS     (2 * NTILES)
#define TPB       (WARPS * 32)       // 640
#define PSTRIDE   36

typedef unsigned long long u64;

__device__ float g_D[N_NODES * N_NODES];
__device__ float g_R[N_NODES * N_NODES];
__device__ float g_DC[N_NODES * N_CLASSES];
__device__ float g_RC[N_NODES * N_CLASSES];
__device__ float g_par[256];
__device__ unsigned int g_ctr;

// ---------------------------------------------------------------------------
__global__ void fractal_setup_kernel(const float* __restrict__ sp,
                                     const float* __restrict__ dir_logits,
                                     const float* __restrict__ class_logits,
                                     const float* __restrict__ child_logits) {
    __shared__ float sCP[N_NODES * N_CLASSES];
    int t = threadIdx.x;
    if (t == 0) g_ctr = 0u;          // reset work queue every launch

    {
        const float* cr = class_logits + t * N_CLASSES;
        float m = -1e30f;
        for (int i = 0; i < N_CLASSES; i++) m = fmaxf(m, cr[i]);
        float s = 0.0f;
        for (int i = 0; i < N_CLASSES; i++) s += expf(cr[i] - m);
        float inv = 1.0f / s;
        for (int i = 0; i < N_CLASSES; i++) sCP[t * N_CLASSES + i] = expf(cr[i] - m) * inv;
    }
    __syncthreads();

    const float* lr = child_logits + (size_t)t * 2 * N_NODES;
    const float* rr = lr + N_NODES;
    float Lv[64], Rv[64], Dv[64];
    {
        float m = -1e30f;
        for (int i = 0; i < 64; i++) m = fmaxf(m, lr[i]);
        float s = 0.0f;
        for (int i = 0; i < 64; i++) s += expf(lr[i] - m);
        float inv = 1.0f / s;
        for (int i = 0; i < 64; i++) Lv[i] = expf(lr[i] - m) * inv;
    }
    {
        float m = -1e30f;
        for (int i = 0; i < 64; i++) m = fmaxf(m, rr[i]);
        float s = 0.0f;
        for (int i = 0; i < 64; i++) s += expf(rr[i] - m);
        float inv = 1.0f / s;
        for (int i = 0; i < 64; i++) Rv[i] = expf(rr[i] - m) * inv;
    }
    for (int i = 0; i < 64; i++) {
        Dv[i] = Lv[i] - Rv[i];
        g_D[t * 64 + i] = Dv[i];
        g_R[t * 64 + i] = Rv[i];
    }
    for (int jc = 0; jc < N_CLASSES; jc++) {
        float ds = 0.0f, rs = 0.0f;
        for (int j = 0; j < 64; j++) {
            ds += Dv[j] * sCP[j * N_CLASSES + jc];
            rs += Rv[j] * sCP[j * N_CLASSES + jc];
        }
        g_DC[t * N_CLASSES + jc] = ds;
        g_RC[t * N_CLASSES + jc] = rs;
    }
    g_par[t]      = expf(-sp[t]);
    g_par[64 + t] = 1.0f / (1.0f + expf(-dir_logits[t]));
    if (t == 0)
        for (int j = 0; j < 64; j++) { g_par[128 + j] = Dv[j]; g_par[192 + j] = Rv[j]; }
}

#define FMA2(acc, a, b) \
    asm("fma.rn.f32x2 %0, %1, %2, %0;" : "+l"(acc) : "l"(a), "l"(b))
#define MUL2(d, a, b) \
    asm("mul.rn.f32x2 %0, %1, %2;" : "=l"(d) : "l"(a), "l"(b))
#define PACK_DUP(d, s) \
    asm("mov.b64 %0, {%1, %1};" : "=l"(d) : "f"(s))
#define UNPACK2(lo, hi, v) \
    asm("mov.b64 {%0, %1}, %2;" : "=f"(lo), "=f"(hi) : "l"(v))
#define PAIR_BAR(tile) \
    asm volatile("bar.sync %0, 64;" :: "r"((tile) + 1) : "memory")

__device__ __forceinline__ int decode_depth(const void* mdp) {
    int v = *reinterpret_cast<const int*>(mdp);
    if (v >= 1 && v <= 1000) return v;
    float f = __int_as_float(v);
    if (f >= 1.0f && f <= 1000.0f) return (int)f;
    return 10;
}

// smem floats: Ds 4096 | Rs 4096 | DCs 1024 | RCs 1024 | PAR 256 | IDX 16 |
//              state NTILES * 2 * 64 * PSTRIDE
#define SMEM_FLOATS (4096 + 4096 + 1024 + 1024 + 256 + 16 + NTILES * 2 * 64 * PSTRIDE)
#define SMEM_BYTES  (SMEM_FLOATS * 4)

__global__ __launch_bounds__(TPB, 1)
void fractal_main_kernel(const float* __restrict__ x_pos,
                         const float* __restrict__ y_pos,
                         const void*  __restrict__ max_depth_ptr,
                         float* __restrict__ out,
                         int B, int ntiles_total) {
    extern __shared__ float sm[];
    float*        Ds   = sm;
    float*        Rs   = Ds + 4096;
    float*        DCs  = Rs + 4096;
    float*        RCs  = DCs + 1024;
    float*        PAR  = RCs + 1024;
    unsigned int* sIdx = reinterpret_cast<unsigned int*>(PAR + 256);   // [NTILES]
    float*        ST   = PAR + 256 + 16;

    const int tid  = threadIdx.x;
    const int wid  = tid >> 5;
    const int lane = tid & 31;
    const int tile = wid >> 1;
    const int sub  = wid & 1;
    const int cb   = sub * 32;
    const int cg   = lane & 7;
    const int pg   = lane >> 3;

    for (int i = tid; i < 4096; i += TPB) { Ds[i] = g_D[i]; Rs[i] = g_R[i]; }
    for (int i = tid; i < 1024; i += TPB) { DCs[i] = g_DC[i]; RCs[i] = g_RC[i]; }
    if (tid < 256) PAR[tid] = g_par[tid];
    __syncthreads();

    float* Pw  = ST + tile * (2 * 64 * PSTRIDE);
    float* Lfw = Pw + 64 * PSTRIDE;

    int md = decode_depth(max_depth_ptr);
    if (md < 2) md = 2;
    const int full_iters = md - 2;

    const float* pbase = Pw + 8 * pg;
    const float* lbase = Lfw + 8 * pg;

    // --------------- dynamic tile loop ---------------
    while (true) {
        if (sub == 0 && lane == 0)
            sIdx[tile] = atomicAdd(&g_ctr, 1u);
        PAIR_BAR(tile);
        const unsigned int ti = sIdx[tile];
        if (ti >= (unsigned int)ntiles_total) break;

        const long long my_pt = (long long)ti * 32 + lane;
        const bool inr = (my_pt < B);

        const float x = inr ? x_pos[my_pt] : 0.5f;
        const float y = inr ? y_pos[my_pt] : 0.5f;
        const float ex = __expf(x), ey = __expf(y);

        float l0;
        {
            float t0 = PAR[0], d0 = PAR[64];
            float hl = __fdividef(1.0f, 1.0f + ex * t0);
            float vl = __fdividef(1.0f, 1.0f + ey * t0);
            l0 = hl + d0 * (vl - hl);
        }
        // init split by node half: sub 0 -> nodes 0..31, sub 1 -> nodes 32..63
        #pragma unroll 8
        for (int k = 0; k < 32; ++k) {
            int n = cb + k;
            float tn = PAR[n], d = PAR[64 + n];
            float hl = __fdividef(1.0f, 1.0f + ex * tn);
            float vl = __fdividef(1.0f, 1.0f + ey * tn);
            Lfw[n * PSTRIDE + lane] = hl + d * (vl - hl);
            Pw[n * PSTRIDE + lane]  = fmaf(l0, PAR[128 + n], PAR[192 + n]);
        }
        PAIR_BAR(tile);

        // ------- full iterations: acc[c][q], c = 4 cols (cb+4cg+c), q = 4 pt-pairs
        for (int it = 0; it < full_iters; ++it) {
            u64 acc[4][4];
            #pragma unroll
            for (int c = 0; c < 4; c++)
                #pragma unroll
                for (int q = 0; q < 4; q++) acc[c][q] = 0ull;

            #pragma unroll 8
            for (int n = 0; n < N_NODES; ++n) {
                ulonglong2 dt = *reinterpret_cast<const ulonglong2*>(Ds + n * 64 + cb + 4 * cg);
                ulonglong2 rt = *reinterpret_cast<const ulonglong2*>(Rs + n * 64 + cb + 4 * cg);

                const float* prow = pbase + n * PSTRIDE;
                const float* lrow = lbase + n * PSTRIDE;
                ulonglong2 pA = *reinterpret_cast<const ulonglong2*>(prow);
                ulonglong2 pB = *reinterpret_cast<const ulonglong2*>(prow + 4);
                ulonglong2 lA = *reinterpret_cast<const ulonglong2*>(lrow);
                ulonglong2 lB = *reinterpret_cast<const ulonglong2*>(lrow + 4);

                u64 p2[4] = { pA.x, pA.y, pB.x, pB.y };
                u64 l2[4] = { lA.x, lA.y, lB.x, lB.y };
                u64 a2[4];
                #pragma unroll
                for (int q = 0; q < 4; q++) MUL2(a2[q], p2[q], l2[q]);

                float dsc[4], rsc[4];
                UNPACK2(dsc[0], dsc[1], dt.x); UNPACK2(dsc[2], dsc[3], dt.y);
                UNPACK2(rsc[0], rsc[1], rt.x); UNPACK2(rsc[2], rsc[3], rt.y);

                #pragma unroll
                for (int c = 0; c < 4; c++) {
                    u64 dd, rr;
                    PACK_DUP(dd, dsc[c]);
                    PACK_DUP(rr, rsc[c]);
                    #pragma unroll
                    for (int q = 0; q < 4; q++) {
                        FMA2(acc[c][q], a2[q], dd);
                        FMA2(acc[c][q], p2[q], rr);
                    }
                }
            }

            PAIR_BAR(tile);
            #pragma unroll
            for (int c = 0; c < 4; c++) {
                int col = cb + 4 * cg + c;
                ulonglong2* dst = reinterpret_cast<ulonglong2*>(Pw + col * PSTRIDE + 8 * pg);
                ulonglong2 v0; v0.x = acc[c][0]; v0.y = acc[c][1];
                ulonglong2 v1; v1.x = acc[c][2]; v1.y = acc[c][3];
                dst[0] = v0;
                dst[1] = v1;
            }
            PAIR_BAR(tile);
        }

        // ------- folded final step: 1 class per lane (cls = 8*sub + cg) -------
        {
            const int cls = 8 * sub + cg;
            u64 fac[4];
            #pragma unroll
            for (int q = 0; q < 4; q++) fac[q] = 0ull;

            #pragma unroll 8
            for (int n = 0; n < N_NODES; ++n) {
                float dcv = DCs[n * N_CLASSES + cls];
                float rcv = RCs[n * N_CLASSES + cls];

                const float* prow = pbase + n * PSTRIDE;
                const float* lrow = lbase + n * PSTRIDE;
                ulonglong2 pA = *reinterpret_cast<const ulonglong2*>(prow);
                ulonglong2 pB = *reinterpret_cast<const ulonglong2*>(prow + 4);
                ulonglong2 lA = *reinterpret_cast<const ulonglong2*>(lrow);
                ulonglong2 lB = *reinterpret_cast<const ulonglong2*>(lrow + 4);

                u64 p2[4] = { pA.x, pA.y, pB.x, pB.y };
                u64 l2[4] = { lA.x, lA.y, lB.x, lB.y };
                u64 a2[4];
                #pragma unroll
                for (int q = 0; q < 4; q++) MUL2(a2[q], p2[q], l2[q]);

                u64 dd, rr;
                PACK_DUP(dd, dcv);
                PACK_DUP(rr, rcv);
                #pragma unroll
                for (int q = 0; q < 4; q++) {
                    FMA2(fac[q], a2[q], dd);
                    FMA2(fac[q], p2[q], rr);
                }
            }

            PAIR_BAR(tile);
            {
                ulonglong2* dst = reinterpret_cast<ulonglong2*>(Pw + cls * PSTRIDE + 8 * pg);
                ulonglong2 v0; v0.x = fac[0]; v0.y = fac[1];
                ulonglong2 v1; v1.x = fac[2]; v1.y = fac[3];
                dst[0] = v0;
                dst[1] = v1;
            }
            PAIR_BAR(tile);
        }

        // ------- gather own point, normalize, store (warp sub==0 only) -------
        if (sub == 0 && inr) {
            float o[16], s = 0.0f;
            #pragma unroll
            for (int c = 0; c < 16; c++) { o[c] = Pw[c * PSTRIDE + lane]; s += o[c]; }
            float inv = 1.0f / fmaxf(s, 1e-10f);
            float4* o4 = reinterpret_cast<float4*>(out + my_pt * N_CLASSES);
            #pragma unroll
            for (int k = 0; k < 4; k++) {
                float4 v;
                v.x = o[4 * k] * inv;     v.y = o[4 * k + 1] * inv;
                v.z = o[4 * k + 2] * inv; v.w = o[4 * k + 3] * inv;
                o4[k] = v;
            }
        }
        PAIR_BAR(tile);   // gather reads + sIdx read done before next fetch/writes
    }
}

// ---------------------------------------------------------------------------
extern "C" void kernel_launch(void* const* d_in, const int* in_sizes, int n_in,
                              void* d_out, int out_size) {
    const float* x_pos = (const float*)d_in[0];
    const float* y_pos = (const float*)d_in[1];
    const float* sp    = (const float*)d_in[2];
    const float* dirl  = (const float*)d_in[3];
    const float* cls   = (const float*)d_in[4];
    const float* child = (const float*)d_in[5];
    const void*  mdp   = d_in[6];
    float* out = (float*)d_out;

    int B = in_sizes[0];
    int ntiles = (B + 31) / 32;
    int grid = (ntiles + NTILES - 1) / NTILES;
    if (grid > 148) grid = 148;

    cudaFuncSetAttribute(fractal_main_kernel,
                         cudaFuncAttributeMaxDynamicSharedMemorySize, SMEM_BYTES);

    fractal_setup_kernel<<<1, 64>>>(sp, dirl, cls, child);

    fractal_main_kernel<<<grid, TPB, SMEM_BYTES>>>(x_pos, y_pos, mdp, out, B, ntiles);
}